// round 12
// baseline (speedup 1.0000x reference)
#include <cuda_runtime.h>
#include <cuda_fp16.h>
#include <cstdint>

#define NN   50000
#define FD   96
#define EMAX 800000
#define SCAN_BLK 512
#define SCAN_NB  ((NN + SCAN_BLK - 1) / SCAN_BLK)   // 98

// ---- device scratch: accessed ONLY from device code ----
__device__ __align__(16) __half sgh_msg1[NN * 96];  // x@w1_l^T (fp16)
__device__ __align__(16) __half sgh_msg2[NN * 48];  // hid@w2_l^T (fp16)
__device__ __align__(16) float sg_root1[NN * 96];   // x@w1_r^T
__device__ __align__(16) float sg_hid[NN * 96];     // layer-1 out
__device__ __align__(16) float sg_root2[NN * 48];   // hid@w2_r^T
__device__ __align__(16) float sg_wt1[FD * 192];    // k-major concat(w1_l,w1_r)
__device__ __align__(16) float sg_wt2[FD * 96];     // k-major concat(w2_l,w2_r)
__device__ int sg_deg[NN];
__device__ int sg_rowptr[NN + 1];
__device__ int sg_cursor[NN];
__device__ int sg_adj[EMAX];
__device__ int sg_src[EMAX];
__device__ int sg_dst[EMAX];
__device__ int sg_part[SCAN_NB];
__device__ int sg_off[SCAN_NB];
__device__ int sg_is64;

__device__ __forceinline__ float* sg_sel(int w) {
    switch (w) {
        case 0: return sg_root1;
        case 1: return sg_hid;
        case 2: return sg_root2;
        case 3: return sg_wt1;
        default: return sg_wt2;
    }
}
__device__ __forceinline__ __half* sgh_sel(int w) {
    return (w == 0) ? sgh_msg1 : sgh_msg2;
}

// ---- init: zero deg + dtype sniff + weight transpose (fused) ----
__global__ void sgv12_init(const int* __restrict__ ei32, int n32,
                           const float* __restrict__ w1_l, const float* __restrict__ w1_r,
                           const float* __restrict__ w2_l, const float* __restrict__ w2_r) {
    int gid = blockIdx.x * blockDim.x + threadIdx.x;
    if (gid < NN) sg_deg[gid] = 0;
    if (gid == 0) {
        int nz = 0;
        int lim = (n32 < 1024) ? n32 : 1024;
        for (int j = 1; j < lim; j += 2) nz |= (ei32[j] != 0);
        sg_is64 = nz ? 0 : 1;
    }
    int stride = gridDim.x * blockDim.x;
    for (int i = gid; i < FD * 192 + FD * 96; i += stride) {
        if (i < FD * 192) {
            int k = i / 192, o = i % 192;
            sg_wt1[i] = (o < 96) ? w1_l[o * FD + k] : w1_r[(o - 96) * FD + k];
        } else {
            int j = i - FD * 192;
            int k = j / 96, o = j % 96;
            sg_wt2[j] = (o < 48) ? w2_l[o * FD + k] : w2_r[(o - 48) * FD + k];
        }
    }
}

__device__ __forceinline__ int sgv12_edge(const void* ei, int idx, int is64) {
    int v = is64 ? (int)((const long long*)ei)[idx] : ((const int*)ei)[idx];
    return min(max(v, 0), NN - 1);
}

// ---- stage edges to clamped int32 + count degrees (fused) ----
__global__ void sgv12_stage(const void* __restrict__ ei, int E) {
    int stride = gridDim.x * blockDim.x;
    int is64 = sg_is64;
    for (int e = blockIdx.x * blockDim.x + threadIdx.x; e < E; e += stride) {
        int s = sgv12_edge(ei, e, is64);
        int d = sgv12_edge(ei, e + E, is64);
        sg_src[e] = s;
        sg_dst[e] = d;
        atomicAdd(&sg_deg[d], 1);
    }
}

// ---- 3-phase scan ----
__global__ void __launch_bounds__(SCAN_BLK) sgv12_scan_a() {
    __shared__ int sm[SCAN_BLK];
    int t = threadIdx.x;
    int i = blockIdx.x * SCAN_BLK + t;
    sm[t] = (i < NN) ? sg_deg[i] : 0;
    __syncthreads();
    for (int off = SCAN_BLK / 2; off > 0; off >>= 1) {
        if (t < off) sm[t] += sm[t + off];
        __syncthreads();
    }
    if (t == 0) sg_part[blockIdx.x] = sm[0];
}

__global__ void __launch_bounds__(128) sgv12_scan_b() {
    __shared__ int sm[128];
    int t = threadIdx.x;
    int v = (t < SCAN_NB) ? sg_part[t] : 0;
    sm[t] = v;
    __syncthreads();
    for (int off = 1; off < 128; off <<= 1) {
        int add = (t >= off) ? sm[t - off] : 0;
        __syncthreads();
        sm[t] += add;
        __syncthreads();
    }
    if (t < SCAN_NB) sg_off[t] = sm[t] - v;
    if (t == 127) sg_rowptr[NN] = sm[127];
}

__global__ void __launch_bounds__(SCAN_BLK) sgv12_scan_c() {
    __shared__ int sm[SCAN_BLK];
    int t = threadIdx.x;
    int i = blockIdx.x * SCAN_BLK + t;
    int v = (i < NN) ? sg_deg[i] : 0;
    sm[t] = v;
    __syncthreads();
    for (int off = 1; off < SCAN_BLK; off <<= 1) {
        int add = (t >= off) ? sm[t - off] : 0;
        __syncthreads();
        sm[t] += add;
        __syncthreads();
    }
    if (i < NN) {
        int excl = sg_off[blockIdx.x] + sm[t] - v;
        sg_rowptr[i] = excl;
        sg_cursor[i] = excl;
    }
}

__global__ void sgv12_bucket(int E) {
    int stride = gridDim.x * blockDim.x;
    for (int e = blockIdx.x * blockDim.x + threadIdx.x; e < E; e += stride) {
        int p = atomicAdd(&sg_cursor[sg_dst[e]], 1);
        sg_adj[p] = sg_src[e];
    }
}

// ---- dual GEMM (R8 config): [Msg(fp16) | Root(fp32)](row,:) = X(row,:) @ WT ----
// WT k-major [FD][OUTT]. Thread: 8 rows x 4 cols. X tile in static smem;
// W streamed via LDG.128 (L1-resident). NO min-blocks bound (R11 lesson).
template <int OUTT, int XSEL, int WSEL, int HSEL, int RSEL>
__global__ void __launch_bounds__(192) sgv12_gemm(const float* __restrict__ Xin) {
    const int TQ = OUTT / 4;        // 48 or 24
    const int TY = 192 / TQ;        // 4 or 8
    const int ROWS = TY * 8;        // 32 or 64
    const int XP = FD + 4;          // 100
    const int HALF = OUTT / 2;

    __shared__ __align__(16) float xs[ROWS * XP];

    const float* X = (XSEL < 0) ? Xin : sg_sel(XSEL);
    const float* WT = sg_sel(WSEL);
    __half* H = sgh_sel(HSEL);
    float* R = sg_sel(RSEL);

    int tid = threadIdx.x;
    int R0 = blockIdx.x * ROWS;

    for (int i = tid; i < ROWS * (FD / 4); i += 192) {
        int r = i / (FD / 4), kc = i % (FD / 4);
        int row = R0 + r;
        float4 v = (row < NN) ? ((const float4*)(X + (size_t)row * FD))[kc]
                              : make_float4(0.f, 0.f, 0.f, 0.f);
        *(float4*)&xs[r * XP + kc * 4] = v;
    }
    __syncthreads();

    int tx = tid % TQ, ty = tid / TQ;
    int c0 = tx * 4, r0 = ty * 8;

    float acc[8][4];
#pragma unroll
    for (int i = 0; i < 8; i++)
#pragma unroll
        for (int j = 0; j < 4; j++) acc[i][j] = 0.f;

#pragma unroll 4
    for (int k = 0; k < FD; k++) {
        float4 w = *(const float4*)&WT[k * OUTT + c0];
#pragma unroll
        for (int i = 0; i < 8; i++) {
            float xv = xs[(r0 + i) * XP + k];
            acc[i][0] = fmaf(w.x, xv, acc[i][0]);
            acc[i][1] = fmaf(w.y, xv, acc[i][1]);
            acc[i][2] = fmaf(w.z, xv, acc[i][2]);
            acc[i][3] = fmaf(w.w, xv, acc[i][3]);
        }
    }

    if (c0 < HALF) {
#pragma unroll
        for (int i = 0; i < 8; i++) {
            int row = R0 + r0 + i;
            if (row >= NN) break;
            __half2 h0 = __floats2half2_rn(acc[i][0], acc[i][1]);
            __half2 h1 = __floats2half2_rn(acc[i][2], acc[i][3]);
            __half2* p = (__half2*)&H[(size_t)row * HALF + c0];
            p[0] = h0;
            p[1] = h1;
        }
    } else {
#pragma unroll
        for (int i = 0; i < 8; i++) {
            int row = R0 + r0 + i;
            if (row >= NN) break;
            *(float4*)&R[(size_t)row * HALF + (c0 - HALF)] =
                make_float4(acc[i][0], acc[i][1], acc[i][2], acc[i][3]);
        }
    }
}

// ---- fused gather (fp16 msgs, uint4 lanes) + fp32 epilogue ----
// O[node] = relu?( mean_j msg[adj[j]] + bias + root[node] )
// One lane covers 8 halves via LDG.128. SUBW=16 (OUT=96, 12 active) / 8 (OUT=48, 6 active).
template <int OUT, int RELU, int HSEL, int RSEL, int OSEL>
__global__ void __launch_bounds__(256) sgv12_gather(const float* __restrict__ bias,
                                                    float* __restrict__ Oext) {
    const int SUBW = (OUT == 96) ? 16 : 8;
    const int VQ8 = OUT / 8;       // active lanes: 12 or 6
    int t = blockIdx.x * 256 + threadIdx.x;
    int node = t / SUBW;
    int sl = t % SUBW;
    if (node >= NN || sl >= VQ8) return;

    const __half* Vh = sgh_sel(HSEL);
    const float* root = sg_sel(RSEL);
    float* O = (OSEL < 0) ? Oext : sg_sel(OSEL);

    int beg = sg_rowptr[node], end = sg_rowptr[node + 1];

    float a[8], b[8];
#pragma unroll
    for (int q = 0; q < 8; q++) { a[q] = 0.f; b[q] = 0.f; }

    int j = beg;
    for (; j + 1 < end; j += 2) {
        uint4 u0 = *(const uint4*)&Vh[(size_t)sg_adj[j] * OUT + sl * 8];
        uint4 u1 = *(const uint4*)&Vh[(size_t)sg_adj[j + 1] * OUT + sl * 8];
        const __half2* h0 = (const __half2*)&u0;
        const __half2* h1 = (const __half2*)&u1;
#pragma unroll
        for (int q = 0; q < 4; q++) {
            float2 f0 = __half22float2(h0[q]);
            float2 f1 = __half22float2(h1[q]);
            a[2 * q] += f0.x;     a[2 * q + 1] += f0.y;
            b[2 * q] += f1.x;     b[2 * q + 1] += f1.y;
        }
    }
    if (j < end) {
        uint4 u0 = *(const uint4*)&Vh[(size_t)sg_adj[j] * OUT + sl * 8];
        const __half2* h0 = (const __half2*)&u0;
#pragma unroll
        for (int q = 0; q < 4; q++) {
            float2 f0 = __half22float2(h0[q]);
            a[2 * q] += f0.x;
            a[2 * q + 1] += f0.y;
        }
    }

    float inv = 1.f / fmaxf((float)(end - beg), 1.f);
    float4 rt0 = *(const float4*)&root[(size_t)node * OUT + sl * 8];
    float4 rt1 = *(const float4*)&root[(size_t)node * OUT + sl * 8 + 4];
    float4 bb0 = *(const float4*)&bias[sl * 8];
    float4 bb1 = *(const float4*)&bias[sl * 8 + 4];
    float4 v0, v1;
    v0.x = (a[0] + b[0]) * inv + rt0.x + bb0.x;
    v0.y = (a[1] + b[1]) * inv + rt0.y + bb0.y;
    v0.z = (a[2] + b[2]) * inv + rt0.z + bb0.z;
    v0.w = (a[3] + b[3]) * inv + rt0.w + bb0.w;
    v1.x = (a[4] + b[4]) * inv + rt1.x + bb1.x;
    v1.y = (a[5] + b[5]) * inv + rt1.y + bb1.y;
    v1.z = (a[6] + b[6]) * inv + rt1.z + bb1.z;
    v1.w = (a[7] + b[7]) * inv + rt1.w + bb1.w;
    if (RELU) {
        v0.x = fmaxf(v0.x, 0.f); v0.y = fmaxf(v0.y, 0.f);
        v0.z = fmaxf(v0.z, 0.f); v0.w = fmaxf(v0.w, 0.f);
        v1.x = fmaxf(v1.x, 0.f); v1.y = fmaxf(v1.y, 0.f);
        v1.z = fmaxf(v1.z, 0.f); v1.w = fmaxf(v1.w, 0.f);
    }
    *(float4*)&O[(size_t)node * OUT + sl * 8] = v0;
    *(float4*)&O[(size_t)node * OUT + sl * 8 + 4] = v1;
}

extern "C" void kernel_launch(void* const* d_in, const int* in_sizes, int n_in,
                              void* d_out, int out_size) {
    const float* x    = (const float*)d_in[0];
    const void*  ei   = d_in[1];
    const float* w1_l = (const float*)d_in[2];
    const float* b1   = (const float*)d_in[3];
    const float* w1_r = (const float*)d_in[4];
    const float* w2_l = (const float*)d_in[5];
    const float* b2   = (const float*)d_in[6];
    const float* w2_r = (const float*)d_in[7];
    float*       out  = (float*)d_out;

    int E = in_sizes[1] / 2;
    if (E > EMAX) E = EMAX;

    const int g1_blocks = (NN + 31) / 32;            // OUTT=192, ROWS=32
    const int g2_blocks = (NN + 63) / 64;            // OUTT=96,  ROWS=64
    const int ga96_blocks = (NN * 16 + 255) / 256;   // SUBW=16
    const int ga48_blocks = (NN * 8 + 255) / 256;    // SUBW=8

    sgv12_init<<<SCAN_NB, SCAN_BLK>>>((const int*)ei, in_sizes[1], w1_l, w1_r, w2_l, w2_r);
    sgv12_stage<<<1024, 256>>>(ei, E);
    sgv12_scan_a<<<SCAN_NB, SCAN_BLK>>>();
    // heavy GEMM as launch #4 (profiler window)
    sgv12_gemm<192, -1, 3, 0, 0><<<g1_blocks, 192>>>(x);
    sgv12_scan_b<<<1, 128>>>();
    sgv12_scan_c<<<SCAN_NB, SCAN_BLK>>>();
    sgv12_bucket<<<1024, 256>>>(E);

    // Layer 1: hid = relu(mean(msg1) + b1 + root1)
    sgv12_gather<96, 1, 0, 0, 1><<<ga96_blocks, 256>>>(b1, nullptr);

    // Layer 2: [msg2(fp16) | root2] = hid @ wt2 ; out = mean(msg2) + b2 + root2
    sgv12_gemm<96, 1, 4, 1, 2><<<g2_blocks, 192>>>(nullptr);
    sgv12_gather<48, 0, 1, 2, -1><<<ga48_blocks, 256>>>(b2, out);
}

// round 13
// speedup vs baseline: 1.0899x; 1.0899x over previous
#include <cuda_runtime.h>
#include <cuda_fp16.h>
#include <cstdint>

#define NN   50000
#define FD   96
#define EMAX 800000
#define SCAN_BLK 512
#define SCAN_NB  ((NN + SCAN_BLK - 1) / SCAN_BLK)   // 98

// ---- device scratch: accessed ONLY from device code ----
__device__ __align__(16) float sg_msg1f[NN * 96];   // x@w1_l^T (fp32, gemm out)
__device__ __align__(16) float sg_root1[NN * 96];   // x@w1_r^T
__device__ __align__(16) float sg_hid[NN * 96];     // layer-1 out
__device__ __align__(16) float sg_msg2f[NN * 48];   // hid@w2_l^T (fp32, gemm out)
__device__ __align__(16) float sg_root2[NN * 48];   // hid@w2_r^T
__device__ __align__(16) float sg_wt1[FD * 192];    // k-major concat(w1_l,w1_r)
__device__ __align__(16) float sg_wt2[FD * 96];     // k-major concat(w2_l,w2_r)
__device__ __align__(16) __half sgh_msg1[NN * 96];  // fp16 copy for gather
__device__ __align__(16) __half sgh_msg2[NN * 48];
__device__ int sg_deg[NN];
__device__ int sg_rowptr[NN + 1];
__device__ int sg_cursor[NN];
__device__ int sg_adj[EMAX];
__device__ int sg_part[SCAN_NB];
__device__ int sg_is64;

__device__ __forceinline__ float* sg_sel(int w) {
    switch (w) {
        case 0: return sg_msg1f;
        case 1: return sg_root1;
        case 2: return sg_hid;
        case 3: return sg_msg2f;
        case 4: return sg_root2;
        case 5: return sg_wt1;
        default: return sg_wt2;
    }
}
__device__ __forceinline__ __half* sgh_sel(int w) {
    return (w == 0) ? sgh_msg1 : sgh_msg2;
}

// ---- init: zero deg + dtype sniff + weight transpose (fused) ----
__global__ void sgv13_init(const int* __restrict__ ei32, int n32,
                           const float* __restrict__ w1_l, const float* __restrict__ w1_r,
                           const float* __restrict__ w2_l, const float* __restrict__ w2_r) {
    int gid = blockIdx.x * blockDim.x + threadIdx.x;
    if (gid < NN) sg_deg[gid] = 0;
    if (gid == 0) {
        int nz = 0;
        int lim = (n32 < 1024) ? n32 : 1024;
        for (int j = 1; j < lim; j += 2) nz |= (ei32[j] != 0);
        sg_is64 = nz ? 0 : 1;
    }
    int stride = gridDim.x * blockDim.x;
    for (int i = gid; i < FD * 192 + FD * 96; i += stride) {
        if (i < FD * 192) {
            int k = i / 192, o = i % 192;
            sg_wt1[i] = (o < 96) ? w1_l[o * FD + k] : w1_r[(o - 96) * FD + k];
        } else {
            int j = i - FD * 192;
            int k = j / 96, o = j % 96;
            sg_wt2[j] = (o < 48) ? w2_l[o * FD + k] : w2_r[(o - 48) * FD + k];
        }
    }
}

__device__ __forceinline__ int sgv13_edge(const void* ei, int idx, int is64) {
    int v = is64 ? (int)((const long long*)ei)[idx] : ((const int*)ei)[idx];
    return min(max(v, 0), NN - 1);
}

__global__ void sgv13_count(const void* __restrict__ ei, int E) {
    int stride = gridDim.x * blockDim.x;
    int is64 = sg_is64;
    for (int e = blockIdx.x * blockDim.x + threadIdx.x; e < E; e += stride)
        atomicAdd(&sg_deg[sgv13_edge(ei, e + E, is64)], 1);
}

// ---- 2-phase scan: per-block partials, then per-block prefix-of-parts + local scan ----
__global__ void __launch_bounds__(SCAN_BLK) sgv13_scan_a() {
    __shared__ int sm[SCAN_BLK];
    int t = threadIdx.x;
    int i = blockIdx.x * SCAN_BLK + t;
    sm[t] = (i < NN) ? sg_deg[i] : 0;
    __syncthreads();
    for (int off = SCAN_BLK / 2; off > 0; off >>= 1) {
        if (t < off) sm[t] += sm[t + off];
        __syncthreads();
    }
    if (t == 0) sg_part[blockIdx.x] = sm[0];
}

__global__ void __launch_bounds__(SCAN_BLK) sgv13_scan_c() {
    __shared__ int sm[SCAN_BLK];
    __shared__ int soff;
    int t = threadIdx.x;
    int bid = blockIdx.x;
    // prefix of partials: sum sg_part[0..bid-1]
    int pv = (t < bid) ? sg_part[t] : 0;    // SCAN_NB=98 < SCAN_BLK
    sm[t] = pv;
    __syncthreads();
    for (int off = SCAN_BLK / 2; off > 0; off >>= 1) {
        if (t < off) sm[t] += sm[t + off];
        __syncthreads();
    }
    if (t == 0) soff = sm[0];
    __syncthreads();
    int off0 = soff;
    // local inclusive scan of this block's deg chunk
    int i = bid * SCAN_BLK + t;
    int v = (i < NN) ? sg_deg[i] : 0;
    sm[t] = v;
    __syncthreads();
    for (int off = 1; off < SCAN_BLK; off <<= 1) {
        int add = (t >= off) ? sm[t - off] : 0;
        __syncthreads();
        sm[t] += add;
        __syncthreads();
    }
    if (i < NN) {
        int excl = off0 + sm[t] - v;
        sg_rowptr[i] = excl;
        sg_cursor[i] = excl;
    }
    if (bid == SCAN_NB - 1 && t == SCAN_BLK - 1)
        sg_rowptr[NN] = off0 + sm[SCAN_BLK - 1];
}

__global__ void sgv13_bucket(const void* __restrict__ ei, int E) {
    int stride = gridDim.x * blockDim.x;
    int is64 = sg_is64;
    for (int e = blockIdx.x * blockDim.x + threadIdx.x; e < E; e += stride) {
        int d = sgv13_edge(ei, e + E, is64);
        int s = sgv13_edge(ei, e, is64);
        int p = atomicAdd(&sg_cursor[d], 1);
        sg_adj[p] = s;
    }
}

// ---- dual GEMM (exact R8): [Oa | Ob](row,:) = X(row,:) @ WT (k-major [FD][OUTT]) ----
template <int OUTT, int XSEL, int WSEL, int OA, int OB>
__global__ void __launch_bounds__(192) sgv13_gemm(const float* __restrict__ Xin) {
    const int TQ = OUTT / 4;        // 48 or 24
    const int TY = 192 / TQ;        // 4 or 8
    const int ROWS = TY * 8;        // 32 or 64
    const int XP = FD + 4;          // 100
    const int HALF = OUTT / 2;

    __shared__ __align__(16) float xs[ROWS * XP];

    const float* X = (XSEL < 0) ? Xin : sg_sel(XSEL);
    const float* WT = sg_sel(WSEL);
    float* Oa = sg_sel(OA);
    float* Ob = sg_sel(OB);

    int tid = threadIdx.x;
    int R0 = blockIdx.x * ROWS;

    for (int i = tid; i < ROWS * (FD / 4); i += 192) {
        int r = i / (FD / 4), kc = i % (FD / 4);
        int row = R0 + r;
        float4 v = (row < NN) ? ((const float4*)(X + (size_t)row * FD))[kc]
                              : make_float4(0.f, 0.f, 0.f, 0.f);
        *(float4*)&xs[r * XP + kc * 4] = v;
    }
    __syncthreads();

    int tx = tid % TQ, ty = tid / TQ;
    int c0 = tx * 4, r0 = ty * 8;

    float acc[8][4];
#pragma unroll
    for (int i = 0; i < 8; i++)
#pragma unroll
        for (int j = 0; j < 4; j++) acc[i][j] = 0.f;

#pragma unroll 4
    for (int k = 0; k < FD; k++) {
        float4 w = *(const float4*)&WT[k * OUTT + c0];
#pragma unroll
        for (int i = 0; i < 8; i++) {
            float xv = xs[(r0 + i) * XP + k];
            acc[i][0] = fmaf(w.x, xv, acc[i][0]);
            acc[i][1] = fmaf(w.y, xv, acc[i][1]);
            acc[i][2] = fmaf(w.z, xv, acc[i][2]);
            acc[i][3] = fmaf(w.w, xv, acc[i][3]);
        }
    }

    float* Obase = (c0 < HALF) ? (Oa + c0) : (Ob + (c0 - HALF));
#pragma unroll
    for (int i = 0; i < 8; i++) {
        int row = R0 + r0 + i;
        if (row >= NN) break;
        *(float4*)&Obase[(size_t)row * HALF] =
            make_float4(acc[i][0], acc[i][1], acc[i][2], acc[i][3]);
    }
}

// ---- fp32 -> fp16 convert (elementwise, float4 -> 4 halves) ----
template <int TOT, int FSEL, int HSEL>
__global__ void __launch_bounds__(256) sgv13_conv() {
    const float4* src = (const float4*)sg_sel(FSEL);
    uint2* dst = (uint2*)sgh_sel(HSEL);
    int stride = gridDim.x * blockDim.x;
    for (int i = blockIdx.x * blockDim.x + threadIdx.x; i < TOT / 4; i += stride) {
        float4 v = src[i];
        __half2 h0 = __floats2half2_rn(v.x, v.y);
        __half2 h1 = __floats2half2_rn(v.z, v.w);
        uint2 u;
        u.x = *(uint32_t*)&h0;
        u.y = *(uint32_t*)&h1;
        dst[i] = u;
    }
}

// ---- fused gather (exact R11 shape: fp16 msgs, uint2 lanes) + fp32 epilogue ----
template <int OUT, int RELU, int HSEL, int RSEL, int OSEL>
__global__ void __launch_bounds__(256) sgv13_gather(const float* __restrict__ bias,
                                                    float* __restrict__ Oext) {
    const int SUBW = (OUT == 96) ? 32 : 16;
    const int VQ = OUT / 4;        // active lanes: 24 or 12
    int t = blockIdx.x * 256 + threadIdx.x;
    int node = t / SUBW;
    int sl = t % SUBW;
    if (node >= NN || sl >= VQ) return;

    const __half* Vh = sgh_sel(HSEL);
    const float* root = sg_sel(RSEL);
    float* O = (OSEL < 0) ? Oext : sg_sel(OSEL);

    int beg = sg_rowptr[node], end = sg_rowptr[node + 1];

    float4 a = make_float4(0.f, 0.f, 0.f, 0.f);
    float4 b = make_float4(0.f, 0.f, 0.f, 0.f);
    int j = beg;
    for (; j + 1 < end; j += 2) {
        uint2 u0 = *(const uint2*)&Vh[(size_t)sg_adj[j] * OUT + sl * 4];
        uint2 u1 = *(const uint2*)&Vh[(size_t)sg_adj[j + 1] * OUT + sl * 4];
        float2 f00 = __half22float2(*(__half2*)&u0.x);
        float2 f01 = __half22float2(*(__half2*)&u0.y);
        float2 f10 = __half22float2(*(__half2*)&u1.x);
        float2 f11 = __half22float2(*(__half2*)&u1.y);
        a.x += f00.x; a.y += f00.y; a.z += f01.x; a.w += f01.y;
        b.x += f10.x; b.y += f10.y; b.z += f11.x; b.w += f11.y;
    }
    if (j < end) {
        uint2 u0 = *(const uint2*)&Vh[(size_t)sg_adj[j] * OUT + sl * 4];
        float2 f00 = __half22float2(*(__half2*)&u0.x);
        float2 f01 = __half22float2(*(__half2*)&u0.y);
        a.x += f00.x; a.y += f00.y; a.z += f01.x; a.w += f01.y;
    }
    float inv = 1.f / fmaxf((float)(end - beg), 1.f);
    float4 rt = *(const float4*)&root[(size_t)node * OUT + sl * 4];
    float4 bb = *(const float4*)&bias[sl * 4];
    float4 v;
    v.x = (a.x + b.x) * inv + rt.x + bb.x;
    v.y = (a.y + b.y) * inv + rt.y + bb.y;
    v.z = (a.z + b.z) * inv + rt.z + bb.z;
    v.w = (a.w + b.w) * inv + rt.w + bb.w;
    if (RELU) {
        v.x = fmaxf(v.x, 0.f); v.y = fmaxf(v.y, 0.f);
        v.z = fmaxf(v.z, 0.f); v.w = fmaxf(v.w, 0.f);
    }
    *(float4*)&O[(size_t)node * OUT + sl * 4] = v;
}

extern "C" void kernel_launch(void* const* d_in, const int* in_sizes, int n_in,
                              void* d_out, int out_size) {
    const float* x    = (const float*)d_in[0];
    const void*  ei   = d_in[1];
    const float* w1_l = (const float*)d_in[2];
    const float* b1   = (const float*)d_in[3];
    const float* w1_r = (const float*)d_in[4];
    const float* w2_l = (const float*)d_in[5];
    const float* b2   = (const float*)d_in[6];
    const float* w2_r = (const float*)d_in[7];
    float*       out  = (float*)d_out;

    int E = in_sizes[1] / 2;
    if (E > EMAX) E = EMAX;

    const int g1_blocks = (NN + 31) / 32;            // OUTT=192, ROWS=32
    const int g2_blocks = (NN + 63) / 64;            // OUTT=96,  ROWS=64
    const int ga96_blocks = (NN * 32 + 255) / 256;   // SUBW=32
    const int ga48_blocks = (NN * 16 + 255) / 256;   // SUBW=16

    sgv13_init<<<SCAN_NB, SCAN_BLK>>>((const int*)ei, in_sizes[1], w1_l, w1_r, w2_l, w2_r);
    sgv13_count<<<1024, 256>>>(ei, E);
    sgv13_scan_a<<<SCAN_NB, SCAN_BLK>>>();
    // heavy GEMM as launch #4 (profiler window)
    sgv13_gemm<192, -1, 5, 0, 1><<<g1_blocks, 192>>>(x);
    sgv13_scan_c<<<SCAN_NB, SCAN_BLK>>>();
    sgv13_bucket<<<1024, 256>>>(ei, E);
    sgv13_conv<NN * 96, 0, 0><<<1024, 256>>>();

    // Layer 1: hid = relu(mean(msg1) + b1 + root1)
    sgv13_gather<96, 1, 0, 1, 2><<<ga96_blocks, 256>>>(b1, nullptr);

    // Layer 2: [msg2f | root2] = hid @ wt2 ; convert ; out = mean(msg2) + b2 + root2
    sgv13_gemm<96, 2, 6, 3, 4><<<g2_blocks, 192>>>(nullptr);
    sgv13_conv<NN * 48, 3, 1><<<512, 256>>>();
    sgv13_gather<48, 0, 1, 4, -1><<<ga48_blocks, 256>>>(b2, out);
}

// round 14
// speedup vs baseline: 1.1848x; 1.0871x over previous
#include <cuda_runtime.h>
#include <cuda_fp16.h>
#include <cstdint>

#define NN   50000
#define FD   96
#define EMAX 800000
#define SCAN_BLK 512
#define SCAN_NB  ((NN + SCAN_BLK - 1) / SCAN_BLK)   // 98

// ---- device scratch: accessed ONLY from device code ----
__device__ __align__(16) float sg_msg1f[NN * 96];   // x@w1_l^T (fp32, gemm out)
__device__ __align__(16) float sg_root1[NN * 96];   // x@w1_r^T
__device__ __align__(16) float sg_hid[NN * 96];     // layer-1 out
__device__ __align__(16) float sg_msg2f[NN * 48];   // hid@w2_l^T (fp32, gemm out)
__device__ __align__(16) float sg_root2[NN * 48];   // hid@w2_r^T
__device__ __align__(16) float sg_wt1[FD * 192];    // k-major concat(w1_l,w1_r)
__device__ __align__(16) float sg_wt2[FD * 96];     // k-major concat(w2_l,w2_r)
__device__ __align__(16) __half sgh_msg1[NN * 96];  // fp16 copy for gather
__device__ __align__(16) __half sgh_msg2[NN * 48];
__device__ int sg_deg[NN];
__device__ int sg_rowptr[NN + 1];
__device__ int sg_cursor[NN];
__device__ int sg_adj[EMAX];
__device__ int sg_part[SCAN_NB];
__device__ int sg_is64;

__device__ __forceinline__ float* sg_sel(int w) {
    switch (w) {
        case 0: return sg_msg1f;
        case 1: return sg_root1;
        case 2: return sg_hid;
        case 3: return sg_msg2f;
        case 4: return sg_root2;
        case 5: return sg_wt1;
        default: return sg_wt2;
    }
}
__device__ __forceinline__ __half* sgh_sel(int w) {
    return (w == 0) ? sgh_msg1 : sgh_msg2;
}

// ---- init: zero deg + dtype sniff + weight transpose (fused) ----
__global__ void sgv14_init(const int* __restrict__ ei32, int n32,
                           const float* __restrict__ w1_l, const float* __restrict__ w1_r,
                           const float* __restrict__ w2_l, const float* __restrict__ w2_r) {
    int gid = blockIdx.x * blockDim.x + threadIdx.x;
    if (gid < NN) sg_deg[gid] = 0;
    if (gid == 0) {
        int nz = 0;
        int lim = (n32 < 1024) ? n32 : 1024;
        for (int j = 1; j < lim; j += 2) nz |= (ei32[j] != 0);
        sg_is64 = nz ? 0 : 1;
    }
    int stride = gridDim.x * blockDim.x;
    for (int i = gid; i < FD * 192 + FD * 96; i += stride) {
        if (i < FD * 192) {
            int k = i / 192, o = i % 192;
            sg_wt1[i] = (o < 96) ? w1_l[o * FD + k] : w1_r[(o - 96) * FD + k];
        } else {
            int j = i - FD * 192;
            int k = j / 96, o = j % 96;
            sg_wt2[j] = (o < 48) ? w2_l[o * FD + k] : w2_r[(o - 48) * FD + k];
        }
    }
}

__device__ __forceinline__ int sgv14_edge(const void* ei, int idx, int is64) {
    int v = is64 ? (int)((const long long*)ei)[idx] : ((const int*)ei)[idx];
    return min(max(v, 0), NN - 1);
}

__global__ void sgv14_count(const void* __restrict__ ei, int E) {
    int stride = gridDim.x * blockDim.x;
    int is64 = sg_is64;
    for (int e = blockIdx.x * blockDim.x + threadIdx.x; e < E; e += stride)
        atomicAdd(&sg_deg[sgv14_edge(ei, e + E, is64)], 1);
}

// ---- 2-phase scan ----
__global__ void __launch_bounds__(SCAN_BLK) sgv14_scan_a() {
    __shared__ int sm[SCAN_BLK];
    int t = threadIdx.x;
    int i = blockIdx.x * SCAN_BLK + t;
    sm[t] = (i < NN) ? sg_deg[i] : 0;
    __syncthreads();
    for (int off = SCAN_BLK / 2; off > 0; off >>= 1) {
        if (t < off) sm[t] += sm[t + off];
        __syncthreads();
    }
    if (t == 0) sg_part[blockIdx.x] = sm[0];
}

__global__ void __launch_bounds__(SCAN_BLK) sgv14_scan_c() {
    __shared__ int sm[SCAN_BLK];
    __shared__ int soff;
    int t = threadIdx.x;
    int bid = blockIdx.x;
    int pv = (t < bid) ? sg_part[t] : 0;    // SCAN_NB=98 < SCAN_BLK
    sm[t] = pv;
    __syncthreads();
    for (int off = SCAN_BLK / 2; off > 0; off >>= 1) {
        if (t < off) sm[t] += sm[t + off];
        __syncthreads();
    }
    if (t == 0) soff = sm[0];
    __syncthreads();
    int off0 = soff;
    int i = bid * SCAN_BLK + t;
    int v = (i < NN) ? sg_deg[i] : 0;
    sm[t] = v;
    __syncthreads();
    for (int off = 1; off < SCAN_BLK; off <<= 1) {
        int add = (t >= off) ? sm[t - off] : 0;
        __syncthreads();
        sm[t] += add;
        __syncthreads();
    }
    if (i < NN) {
        int excl = off0 + sm[t] - v;
        sg_rowptr[i] = excl;
        sg_cursor[i] = excl;
    }
    if (bid == SCAN_NB - 1 && t == SCAN_BLK - 1)
        sg_rowptr[NN] = off0 + sm[SCAN_BLK - 1];
}

__global__ void sgv14_bucket(const void* __restrict__ ei, int E) {
    int stride = gridDim.x * blockDim.x;
    int is64 = sg_is64;
    for (int e = blockIdx.x * blockDim.x + threadIdx.x; e < E; e += stride) {
        int d = sgv14_edge(ei, e + E, is64);
        int s = sgv14_edge(ei, e, is64);
        int p = atomicAdd(&sg_cursor[d], 1);
        sg_adj[p] = s;
    }
}

// ---- dual GEMM (exact R8): [Oa | Ob](row,:) = X(row,:) @ WT (k-major [FD][OUTT]) ----
template <int OUTT, int XSEL, int WSEL, int OA, int OB>
__global__ void __launch_bounds__(192) sgv14_gemm(const float* __restrict__ Xin) {
    const int TQ = OUTT / 4;
    const int TY = 192 / TQ;
    const int ROWS = TY * 8;
    const int XP = FD + 4;
    const int HALF = OUTT / 2;

    __shared__ __align__(16) float xs[ROWS * XP];

    const float* X = (XSEL < 0) ? Xin : sg_sel(XSEL);
    const float* WT = sg_sel(WSEL);
    float* Oa = sg_sel(OA);
    float* Ob = sg_sel(OB);

    int tid = threadIdx.x;
    int R0 = blockIdx.x * ROWS;

    for (int i = tid; i < ROWS * (FD / 4); i += 192) {
        int r = i / (FD / 4), kc = i % (FD / 4);
        int row = R0 + r;
        float4 v = (row < NN) ? ((const float4*)(X + (size_t)row * FD))[kc]
                              : make_float4(0.f, 0.f, 0.f, 0.f);
        *(float4*)&xs[r * XP + kc * 4] = v;
    }
    __syncthreads();

    int tx = tid % TQ, ty = tid / TQ;
    int c0 = tx * 4, r0 = ty * 8;

    float acc[8][4];
#pragma unroll
    for (int i = 0; i < 8; i++)
#pragma unroll
        for (int j = 0; j < 4; j++) acc[i][j] = 0.f;

#pragma unroll 4
    for (int k = 0; k < FD; k++) {
        float4 w = *(const float4*)&WT[k * OUTT + c0];
#pragma unroll
        for (int i = 0; i < 8; i++) {
            float xv = xs[(r0 + i) * XP + k];
            acc[i][0] = fmaf(w.x, xv, acc[i][0]);
            acc[i][1] = fmaf(w.y, xv, acc[i][1]);
            acc[i][2] = fmaf(w.z, xv, acc[i][2]);
            acc[i][3] = fmaf(w.w, xv, acc[i][3]);
        }
    }

    float* Obase = (c0 < HALF) ? (Oa + c0) : (Ob + (c0 - HALF));
#pragma unroll
    for (int i = 0; i < 8; i++) {
        int row = R0 + r0 + i;
        if (row >= NN) break;
        *(float4*)&Obase[(size_t)row * HALF] =
            make_float4(acc[i][0], acc[i][1], acc[i][2], acc[i][3]);
    }
}

// ---- fp32 -> fp16 convert ----
template <int TOT, int FSEL, int HSEL>
__global__ void __launch_bounds__(256) sgv14_conv() {
    const float4* src = (const float4*)sg_sel(FSEL);
    uint2* dst = (uint2*)sgh_sel(HSEL);
    int stride = gridDim.x * blockDim.x;
    for (int i = blockIdx.x * blockDim.x + threadIdx.x; i < TOT / 4; i += stride) {
        float4 v = src[i];
        __half2 h0 = __floats2half2_rn(v.x, v.y);
        __half2 h1 = __floats2half2_rn(v.z, v.w);
        uint2 u;
        u.x = *(uint32_t*)&h0;
        u.y = *(uint32_t*)&h1;
        dst[i] = u;
    }
}

// ---- fused gather (fp16 msgs, uint2 lanes) + fp32 epilogue ----
template <int OUT, int RELU, int HSEL, int RSEL, int OSEL>
__global__ void __launch_bounds__(256) sgv14_gather(const float* __restrict__ bias,
                                                    float* __restrict__ Oext) {
    const int SUBW = (OUT == 96) ? 32 : 16;
    const int VQ = OUT / 4;
    int t = blockIdx.x * 256 + threadIdx.x;
    int node = t / SUBW;
    int sl = t % SUBW;
    if (node >= NN || sl >= VQ) return;

    const __half* Vh = sgh_sel(HSEL);
    const float* root = sg_sel(RSEL);
    float* O = (OSEL < 0) ? Oext : sg_sel(OSEL);

    int beg = sg_rowptr[node], end = sg_rowptr[node + 1];

    float4 a = make_float4(0.f, 0.f, 0.f, 0.f);
    float4 b = make_float4(0.f, 0.f, 0.f, 0.f);
    int j = beg;
    for (; j + 1 < end; j += 2) {
        uint2 u0 = *(const uint2*)&Vh[(size_t)sg_adj[j] * OUT + sl * 4];
        uint2 u1 = *(const uint2*)&Vh[(size_t)sg_adj[j + 1] * OUT + sl * 4];
        float2 f00 = __half22float2(*(__half2*)&u0.x);
        float2 f01 = __half22float2(*(__half2*)&u0.y);
        float2 f10 = __half22float2(*(__half2*)&u1.x);
        float2 f11 = __half22float2(*(__half2*)&u1.y);
        a.x += f00.x; a.y += f00.y; a.z += f01.x; a.w += f01.y;
        b.x += f10.x; b.y += f10.y; b.z += f11.x; b.w += f11.y;
    }
    if (j < end) {
        uint2 u0 = *(const uint2*)&Vh[(size_t)sg_adj[j] * OUT + sl * 4];
        float2 f00 = __half22float2(*(__half2*)&u0.x);
        float2 f01 = __half22float2(*(__half2*)&u0.y);
        a.x += f00.x; a.y += f00.y; a.z += f01.x; a.w += f01.y;
    }
    float inv = 1.f / fmaxf((float)(end - beg), 1.f);
    float4 rt = *(const float4*)&root[(size_t)node * OUT + sl * 4];
    float4 bb = *(const float4*)&bias[sl * 4];
    float4 v;
    v.x = (a.x + b.x) * inv + rt.x + bb.x;
    v.y = (a.y + b.y) * inv + rt.y + bb.y;
    v.z = (a.z + b.z) * inv + rt.z + bb.z;
    v.w = (a.w + b.w) * inv + rt.w + bb.w;
    if (RELU) {
        v.x = fmaxf(v.x, 0.f); v.y = fmaxf(v.y, 0.f);
        v.z = fmaxf(v.z, 0.f); v.w = fmaxf(v.w, 0.f);
    }
    *(float4*)&O[(size_t)node * OUT + sl * 4] = v;
}

extern "C" void kernel_launch(void* const* d_in, const int* in_sizes, int n_in,
                              void* d_out, int out_size) {
    const float* x    = (const float*)d_in[0];
    const void*  ei   = d_in[1];
    const float* w1_l = (const float*)d_in[2];
    const float* b1   = (const float*)d_in[3];
    const float* w1_r = (const float*)d_in[4];
    const float* w2_l = (const float*)d_in[5];
    const float* b2   = (const float*)d_in[6];
    const float* w2_r = (const float*)d_in[7];
    float*       out  = (float*)d_out;

    int E = in_sizes[1] / 2;
    if (E > EMAX) E = EMAX;

    const int g1_blocks = (NN + 31) / 32;
    const int g2_blocks = (NN + 63) / 64;
    const int ga96_blocks = (NN * 32 + 255) / 256;
    const int ga48_blocks = (NN * 16 + 255) / 256;

    // fork-join: CSR chain on a side stream, GEMM chain on the main (default) stream
    cudaStream_t side;
    cudaStreamCreateWithFlags(&side, cudaStreamNonBlocking);
    cudaEvent_t evFork, evJoin;
    cudaEventCreateWithFlags(&evFork, cudaEventDisableTiming);
    cudaEventCreateWithFlags(&evJoin, cudaEventDisableTiming);

    sgv14_init<<<SCAN_NB, SCAN_BLK>>>((const int*)ei, in_sizes[1], w1_l, w1_r, w2_l, w2_r);
    cudaEventRecord(evFork, 0);
    cudaStreamWaitEvent(side, evFork, 0);

    // side branch: CSR build
    sgv14_count<<<1024, 256, 0, side>>>(ei, E);
    sgv14_scan_a<<<SCAN_NB, SCAN_BLK, 0, side>>>();
    sgv14_scan_c<<<SCAN_NB, SCAN_BLK, 0, side>>>();
    sgv14_bucket<<<1024, 256, 0, side>>>(ei, E);
    cudaEventRecord(evJoin, side);

    // main branch: layer-1 GEMM + fp16 convert
    sgv14_gemm<192, -1, 5, 0, 1><<<g1_blocks, 192>>>(x);
    sgv14_conv<NN * 96, 0, 0><<<1024, 256>>>();

    // join, then the serial tail
    cudaStreamWaitEvent(0, evJoin, 0);
    sgv14_gather<96, 1, 0, 1, 2><<<ga96_blocks, 256>>>(b1, nullptr);
    sgv14_gemm<96, 2, 6, 3, 4><<<g2_blocks, 192>>>(nullptr);
    sgv14_conv<NN * 48, 3, 1><<<512, 256>>>();
    sgv14_gather<48, 0, 1, 4, -1><<<ga48_blocks, 256>>>(b2, out);

    // destroy only when not capturing (destroying a capture-associated stream
    // would invalidate the capture); leaked objects are host-side only.
    cudaStreamCaptureStatus st = cudaStreamCaptureStatusNone;
    cudaStreamIsCapturing(side, &st);
    if (st == cudaStreamCaptureStatusNone) {
        cudaStreamDestroy(side);
        cudaEventDestroy(evFork);
        cudaEventDestroy(evJoin);
    }
}